// round 10
// baseline (speedup 1.0000x reference)
#include <cuda_runtime.h>
#include <math.h>
#include <stdint.h>

// ParallelRNN via warp-level tf32 mma.sync. B=4096,H=256,L=32,I=64.
// R10: xi (input-projection) GEMMs precomputed to gmem; main chain = 5 HH
// GEMMs. 64-row CTAs x 256 thr, 97KB smem -> 2 CTAs/SM (desynced barriers).

#define DEVI __device__ __forceinline__

static constexpr long long BHL = 4096LL * 256 * 32;
static constexpr long long BLc = 4096LL * 32;

static constexpr size_t HH_ONE = 32 * 65536;          // floats per HH weight (all l)
static constexpr size_t II_ONE = 32 * 16384;
static constexpr size_t HH_TOT = 5 * HH_ONE;
static constexpr size_t W_TOT  = HH_TOT + 3 * II_ONE;

__device__ float g_wr[W_TOT];                 // fragment-ordered tf32 weights
__device__ float g_scr[33554432];             // per-warp r/n scratch
__device__ float g_xi[3ULL * 32 * 4096 * 256]; // xi_r / xi_n / xi_z (+bias)

// main smem (bytes): A[0,65536) ring 2x16384[65536,98304) mu[98304,98560)
//                    wmu[98560,99584)
static constexpr unsigned SMEM_MAIN = 99584;
// xi smem: xm[0,32768) ring[32768,65536)
static constexpr unsigned SMEM_XI = 65536;

DEVI unsigned s2u(const void* p) {
    unsigned a;
    asm("{ .reg .u64 t; cvta.to.shared.u64 t, %1; cvt.u32.u64 %0, t; }"
        : "=r"(a) : "l"(p));
    return a;
}
DEVI float sigm(float v) { return __fdividef(1.f, 1.f + __expf(-v)); }
DEVI float tf32r(float v) {
    uint32_t o;
    asm("cvt.rna.tf32.f32 %0, %1;" : "=r"(o) : "f"(v));
    return __uint_as_float(o);
}
DEVI unsigned aswz(int row, int k4) {
    return (unsigned)(((k4 & ~7) | ((k4 ^ row) & 7)) * 16);
}

// ---------- prep: fragment-ordered tf32 weight images (same as R9) ----------
__global__ void __launch_bounds__(256)
wprep(const float* __restrict__ Whr, const float* __restrict__ Whn,
      const float* __restrict__ Whz, const float* __restrict__ W1,
      const float* __restrict__ W2,  const float* __restrict__ Wir,
      const float* __restrict__ Win, const float* __restrict__ Wiz) {
    const int bid = blockIdx.x, tid = threadIdx.x;
    const float* src;
    float* dst;
    int c;
    if (bid < 2560) {                 // 5 HH x 32 l x 16 chunks
        int w = bid >> 9, rem = bid & 511, l = rem >> 4;
        c = rem & 15;
        const float* hs[5] = {Whr, Whn, Whz, W1, W2};
        src = hs[w] + (size_t)l * 65536;
        dst = g_wr + (size_t)(w * 32 + l) * 65536 + (size_t)c * 4096;
    } else {                          // 3 II x 32 l x 4 chunks
        int e = bid - 2560;
        int w = e >> 7, rem = e & 127, l = rem >> 2;
        c = rem & 3;
        const float* is[3] = {Wir, Win, Wiz};
        src = is[w] + (size_t)l * 16384;
        dst = g_wr + HH_TOT + (size_t)(w * 32 + l) * 16384 + (size_t)c * 4096;
    }
    const int s = tid >> 7, wc = (tid >> 5) & 3, lane = tid & 31;
#pragma unroll
    for (int j4 = 0; j4 < 4; ++j4) {
        float4 v;
        int k0 = c * 16 + s * 8 + (lane & 3);
        int n0 = wc * 64 + (2 * j4) * 8 + (lane >> 2);
        int n1 = n0 + 8;
        v.x = tf32r(src[(size_t)k0 * 256 + n0]);
        v.y = tf32r(src[(size_t)(k0 + 4) * 256 + n0]);
        v.z = tf32r(src[(size_t)k0 * 256 + n1]);
        v.w = tf32r(src[(size_t)(k0 + 4) * 256 + n1]);
        reinterpret_cast<float4*>(dst)[(s * 4 + j4) * 128 + wc * 32 + lane] = v;
    }
}

// ---- GEMM segment: acc += Asm[rows x 16*nch] @ W[16*nch x 256] ----
// warp tile 32x64 at (wr, wc); A-frags hoisted before wait; ring 2 x 16KB.
template <int RS, int NTHR>
DEVI void gemm_seg(float (&acc)[2][8][4], unsigned aU, const float* __restrict__ W,
                   int nch, unsigned bU, int tid, int lane, int wr, int wc) {
    constexpr int CPB = 16384 / (NTHR * 16);
    {
        const char* s = (const char*)W;
#pragma unroll
        for (int q = 0; q < CPB; ++q)
            asm volatile("cp.async.cg.shared.global [%0], [%1], 16;"
                :: "r"(bU + (unsigned)(q * NTHR + tid) * 16u),
                   "l"(s + (size_t)(q * NTHR + tid) * 16));
        asm volatile("cp.async.commit_group;");
    }
    const int lm = lane >> 3, lr = lane & 7;
    const unsigned bfb = (unsigned)(wc * 32 + lane) * 16u;
    for (int c = 0; c < nch; ++c) {
        uint32_t af[2][2][4];
#pragma unroll
        for (int s = 0; s < 2; ++s)
#pragma unroll
            for (int i = 0; i < 2; ++i) {
                int row = wr * 32 + i * 16 + (lm & 1) * 8 + lr;
                int k4  = c * 4 + s * 2 + (lm >> 1);
                unsigned ad = aU + (unsigned)row * RS + aswz(row, k4);
                asm volatile("ldmatrix.sync.aligned.m8n8.x4.shared.b16 {%0,%1,%2,%3}, [%4];"
                    : "=r"(af[s][i][0]), "=r"(af[s][i][1]),
                      "=r"(af[s][i][2]), "=r"(af[s][i][3])
                    : "r"(ad));
            }
        asm volatile("cp.async.wait_group 0;");
        __syncthreads();
        if (c + 1 < nch) {
            const char* s = (const char*)W + (size_t)(c + 1) * 16384;
            unsigned dst = bU + (unsigned)((c + 1) & 1) * 16384u;
#pragma unroll
            for (int q = 0; q < CPB; ++q)
                asm volatile("cp.async.cg.shared.global [%0], [%1], 16;"
                    :: "r"(dst + (unsigned)(q * NTHR + tid) * 16u),
                       "l"(s + (size_t)(q * NTHR + tid) * 16));
        }
        asm volatile("cp.async.commit_group;");

        const unsigned bb = bU + (unsigned)(c & 1) * 16384u;
#pragma unroll
        for (int s = 0; s < 2; ++s) {
            uint32_t bf[8][2];
#pragma unroll
            for (int j4 = 0; j4 < 4; ++j4) {
                uint32_t v0, v1, v2, v3;
                asm volatile("ld.shared.v4.b32 {%0,%1,%2,%3}, [%4];"
                    : "=r"(v0), "=r"(v1), "=r"(v2), "=r"(v3)
                    : "r"(bb + (unsigned)(s * 4 + j4) * 2048u + bfb));
                bf[2 * j4][0] = v0; bf[2 * j4][1] = v1;
                bf[2 * j4 + 1][0] = v2; bf[2 * j4 + 1][1] = v3;
            }
#pragma unroll
            for (int i = 0; i < 2; ++i)
#pragma unroll
                for (int j = 0; j < 8; ++j)
                    asm volatile(
                        "mma.sync.aligned.m16n8k8.row.col.f32.tf32.tf32.f32 "
                        "{%0,%1,%2,%3}, {%4,%5,%6,%7}, {%8,%9}, {%0,%1,%2,%3};"
                        : "+f"(acc[i][j][0]), "+f"(acc[i][j][1]),
                          "+f"(acc[i][j][2]), "+f"(acc[i][j][3])
                        : "r"(af[s][i][0]), "r"(af[s][i][1]),
                          "r"(af[s][i][2]), "r"(af[s][i][3]),
                          "r"(bf[j][0]), "r"(bf[j][1]));
        }
    }
    __syncthreads();   // A/B reads done before epilogue writes / next segment
}

#define ZACC()                                                                \
    _Pragma("unroll") for (int i = 0; i < 2; ++i)                             \
    _Pragma("unroll") for (int j = 0; j < 8; ++j)                             \
    _Pragma("unroll") for (int q = 0; q < 4; ++q) acc[i][j][q] = 0.f;
#define C0J (wc * 64 + j * 8 + 2 * (lane & 3))
#define R0I (wr * 32 + i * 16 + (lane >> 2))

// ---------- xi kernel: xi_g = xm @ Wig + big  -> g_xi ----------
__global__ void __launch_bounds__(512, 1)
prnn_xi(const float* __restrict__ x, const float* __restrict__ mask,
        const float* __restrict__ bir, const float* __restrict__ bin_,
        const float* __restrict__ biz) {
    extern __shared__ __align__(16) char smem[];
    const unsigned sU = s2u(smem);
    const unsigned xU = sU, bU = sU + 32768u;
    const int tid = threadIdx.x, lane = tid & 31, w = tid >> 5;
    const int wr = w >> 2, wc = w & 3;           // warp grid 4 x 4, rows 0..127
    const int l = blockIdx.x & 31, b0 = (blockIdx.x >> 5) * 128;

    {   // xm <- tf32(x * mask), swizzled
#pragma unroll
        for (int q = 0; q < 16; ++q) {
            int idx = tid + q * 512, r = idx >> 6, k = idx & 63;
            float v = tf32r(__ldg(x + (size_t)(b0 + r) * 64 + k)
                            * __ldg(mask + k * 32 + l));
            unsigned ad = xU + (unsigned)r * 256u + aswz(r, k >> 2) + (k & 3) * 4u;
            asm volatile("st.shared.f32 [%0], %1;" :: "r"(ad), "f"(v));
        }
    }
    __syncthreads();
    const float* WI = g_wr + HH_TOT;
    const float* bias[3] = {bir, bin_, biz};
    float acc[2][8][4];
#pragma unroll 1
    for (int g = 0; g < 3; ++g) {
        ZACC();
        gemm_seg<256, 512>(acc, xU, WI + (size_t)(g * 32 + l) * 16384, 4,
                           bU, tid, lane, wr, wc);
        const float* bb = bias[g] + l * 256;
        float* dst = g_xi + ((size_t)(g * 32 + l) * 4096 + b0) * 256;
#pragma unroll
        for (int i = 0; i < 2; ++i)
#pragma unroll
            for (int j = 0; j < 8; ++j) {
                int c0 = C0J, r0 = R0I, r1 = r0 + 8;
                float2 v0, v1;
                v0.x = acc[i][j][0] + __ldg(bb + c0);
                v0.y = acc[i][j][1] + __ldg(bb + c0 + 1);
                v1.x = acc[i][j][2] + __ldg(bb + c0);
                v1.y = acc[i][j][3] + __ldg(bb + c0 + 1);
                *reinterpret_cast<float2*>(dst + (size_t)r0 * 256 + c0) = v0;
                *reinterpret_cast<float2*>(dst + (size_t)r1 * 256 + c0) = v1;
            }
    }
}

// ---------- main kernel: 5 HH GEMM chain, 64-row CTAs ----------
__global__ void __launch_bounds__(256, 2)
prnn_main(const float* __restrict__ hidden,
          const float* __restrict__ bhn, const float* __restrict__ b1,
          const float* __restrict__ b2,  const float* __restrict__ Wmu,
          const float* __restrict__ bmu, const float* __restrict__ log_var,
          float* __restrict__ out) {
    extern __shared__ __align__(16) char smem[];
    const unsigned sU = s2u(smem);
    const unsigned aU = sU, bU = sU + 65536u;
    float* mu_s  = (float*)(smem + 98304);
    float* wmu_s = (float*)(smem + 98560);
    const int tid = threadIdx.x, lane = tid & 31, w = tid >> 5;
    const int wr = w >> 2, wc = w & 3;           // warp grid 2 x 4, rows 0..63
    const int l = blockIdx.x & 31, b0 = (blockIdx.x >> 6) * 64
                + ((blockIdx.x >> 5) & 1) * 2048;   // spread tiles

    if (tid < 64) mu_s[tid] = 0.f;
    wmu_s[tid] = __ldg(Wmu + l * 256 + tid);

    {   // A <- tf32(h): thread = column, 64 rows
        const float* hp = hidden + (size_t)b0 * 8192 + (size_t)tid * 32 + l;
#pragma unroll 4
        for (int r = 0; r < 64; ++r) {
            float v = tf32r(hp[(size_t)r * 8192]);
            unsigned ad = aU + (unsigned)r * 1024u + aswz(r, tid >> 2)
                        + (tid & 3) * 4u;
            asm volatile("st.shared.f32 [%0], %1;" :: "r"(ad), "f"(v));
        }
    }
    __syncthreads();

    float acc[2][8][4];
    float* scr = g_scr + (size_t)blockIdx.x * 16384 + (size_t)w * 2048;
    const float* WH = g_wr;
    const float* xiR = g_xi + ((size_t)(0 * 32 + l) * 4096 + b0) * 256;
    const float* xiN = g_xi + ((size_t)(1 * 32 + l) * 4096 + b0) * 256;
    const float* xiZ = g_xi + ((size_t)(2 * 32 + l) * 4096 + b0) * 256;
#define SCRP(i, j) (scr + ((size_t)((i) * 8 + (j)) * 32 + lane) * 4)
#define ACC_INIT(src)                                                         \
    _Pragma("unroll") for (int i = 0; i < 2; ++i)                             \
    _Pragma("unroll") for (int j = 0; j < 8; ++j) {                           \
        int c0 = C0J, r0 = R0I;                                               \
        float2 u0 = __ldg((const float2*)((src) + (size_t)r0 * 256 + c0));    \
        float2 u1 = __ldg((const float2*)((src) + (size_t)(r0 + 8) * 256 + c0)); \
        acc[i][j][0] = u0.x; acc[i][j][1] = u0.y;                             \
        acc[i][j][2] = u1.x; acc[i][j][3] = u1.y;                             \
    }

    // seg1: r = sigmoid(xi_r + h@Whr) -> scratch
    ACC_INIT(xiR);
    gemm_seg<1024, 256>(acc, aU, WH + (size_t)(0 * 32 + l) * 65536, 16,
                        bU, tid, lane, wr, wc);
    {
#pragma unroll
        for (int i = 0; i < 2; ++i)
#pragma unroll
            for (int j = 0; j < 8; ++j) {
                float4 v;
                v.x = sigm(acc[i][j][0]);
                v.y = sigm(acc[i][j][1]);
                v.z = sigm(acc[i][j][2]);
                v.w = sigm(acc[i][j][3]);
                *reinterpret_cast<float4*>(SCRP(i, j)) = v;
            }
    }
    // seg2: acc = h@Whn; n = tanh(xi_n + r*(acc+bhn)) -> scratch
    ZACC();
    gemm_seg<1024, 256>(acc, aU, WH + (size_t)(1 * 32 + l) * 65536, 16,
                        bU, tid, lane, wr, wc);
    {
        const float* bb = bhn + l * 256;
#pragma unroll
        for (int i = 0; i < 2; ++i)
#pragma unroll
            for (int j = 0; j < 8; ++j) {
                int c0 = C0J, r0 = R0I;
                float4 rv = *reinterpret_cast<const float4*>(SCRP(i, j));
                float2 n0 = __ldg((const float2*)(xiN + (size_t)r0 * 256 + c0));
                float2 n1 = __ldg((const float2*)(xiN + (size_t)(r0 + 8) * 256 + c0));
                float4 v;
                v.x = tanhf(n0.x + rv.x * (acc[i][j][0] + __ldg(bb + c0)));
                v.y = tanhf(n0.y + rv.y * (acc[i][j][1] + __ldg(bb + c0 + 1)));
                v.z = tanhf(n1.x + rv.z * (acc[i][j][2] + __ldg(bb + c0)));
                v.w = tanhf(n1.y + rv.w * (acc[i][j][3] + __ldg(bb + c0 + 1)));
                *reinterpret_cast<float4*>(SCRP(i, j)) = v;
            }
    }
    // seg3: z = sigmoid(xi_z + h@Whz); hnew = n + z*(h-n) -> A (tf32)
    ACC_INIT(xiZ);
    gemm_seg<1024, 256>(acc, aU, WH + (size_t)(2 * 32 + l) * 65536, 16,
                        bU, tid, lane, wr, wc);
    {
#pragma unroll
        for (int i = 0; i < 2; ++i)
#pragma unroll
            for (int j = 0; j < 8; ++j) {
                int c0 = C0J, r0 = R0I, r1 = r0 + 8;
                float4 nv = *reinterpret_cast<const float4*>(SCRP(i, j));
                float zz[4];
                zz[0] = sigm(acc[i][j][0]);
                zz[1] = sigm(acc[i][j][1]);
                zz[2] = sigm(acc[i][j][2]);
                zz[3] = sigm(acc[i][j][3]);
                const int rr[4] = {r0, r0, r1, r1};
                const int cc[4] = {c0, c0 + 1, c0, c0 + 1};
                const float nn[4] = {nv.x, nv.y, nv.z, nv.w};
#pragma unroll
                for (int q = 0; q < 4; ++q) {
                    unsigned ad = aU + (unsigned)rr[q] * 1024u
                                + aswz(rr[q], cc[q] >> 2) + (cc[q] & 3) * 4u;
                    float h;
                    asm volatile("ld.shared.f32 %0, [%1];" : "=f"(h) : "r"(ad));
                    float hv = tf32r(nn[q] + zz[q] * (h - nn[q]));
                    asm volatile("st.shared.f32 [%0], %1;" :: "r"(ad), "f"(hv));
                }
            }
    }
    __syncthreads();
    // seg4: h1 = relu(hnew@W1 + b1) -> A (tf32)
    ZACC();
    gemm_seg<1024, 256>(acc, aU, WH + (size_t)(3 * 32 + l) * 65536, 16,
                        bU, tid, lane, wr, wc);
    {
        const float* bb = b1 + l * 256;
#pragma unroll
        for (int i = 0; i < 2; ++i)
#pragma unroll
            for (int j = 0; j < 8; ++j) {
                int c0 = C0J, r0 = R0I, r1 = r0 + 8;
                const int rr[4] = {r0, r0, r1, r1};
                const int cc[4] = {c0, c0 + 1, c0, c0 + 1};
#pragma unroll
                for (int q = 0; q < 4; ++q) {
                    float hv = tf32r(fmaxf(acc[i][j][q] + __ldg(bb + cc[q]), 0.f));
                    unsigned ad = aU + (unsigned)rr[q] * 1024u
                                + aswz(rr[q], cc[q] >> 2) + (cc[q] & 3) * 4u;
                    asm volatile("st.shared.f32 [%0], %1;" :: "r"(ad), "f"(hv));
                }
            }
    }
    __syncthreads();
    // seg5: h2 = relu(h1@W2 + b2) -> out + mu
    ZACC();
    gemm_seg<1024, 256>(acc, aU, WH + (size_t)(4 * 32 + l) * 65536, 16,
                        bU, tid, lane, wr, wc);
    {
        const float* bb = b2 + l * 256;
        float mup[2][2];
#pragma unroll
        for (int i = 0; i < 2; ++i) { mup[i][0] = 0.f; mup[i][1] = 0.f; }
#pragma unroll
        for (int i = 0; i < 2; ++i)
#pragma unroll
            for (int j = 0; j < 8; ++j) {
                int c0 = C0J, r0 = R0I, r1 = r0 + 8;
                float h2a = fmaxf(acc[i][j][0] + __ldg(bb + c0), 0.f);
                float h2b = fmaxf(acc[i][j][1] + __ldg(bb + c0 + 1), 0.f);
                float h2c = fmaxf(acc[i][j][2] + __ldg(bb + c0), 0.f);
                float h2d = fmaxf(acc[i][j][3] + __ldg(bb + c0 + 1), 0.f);
                size_t ob  = (size_t)(b0 + r0) * 8192 + l;
                size_t ob1 = (size_t)(b0 + r1) * 8192 + l;
                out[ob + (size_t)c0 * 32]        = h2a;
                out[ob + (size_t)(c0 + 1) * 32]  = h2b;
                out[ob1 + (size_t)c0 * 32]       = h2c;
                out[ob1 + (size_t)(c0 + 1) * 32] = h2d;
                mup[i][0] += h2a * wmu_s[c0] + h2b * wmu_s[c0 + 1];
                mup[i][1] += h2c * wmu_s[c0] + h2d * wmu_s[c0 + 1];
            }
#pragma unroll
        for (int i = 0; i < 2; ++i)
#pragma unroll
            for (int hq = 0; hq < 2; ++hq) {
                float v = mup[i][hq];
                v += __shfl_xor_sync(0xffffffffu, v, 1);
                v += __shfl_xor_sync(0xffffffffu, v, 2);
                if ((lane & 3) == 0)
                    atomicAdd(&mu_s[wr * 32 + i * 16 + (lane >> 2) + hq * 8], v);
            }
    }
    __syncthreads();
    if (tid < 64) {
        out[BHL + (size_t)(b0 + tid) * 32 + l] = mu_s[tid] + __ldg(bmu + l);
        out[BHL + BLc + (size_t)(b0 + tid) * 32 + l] =
            fmaxf(__ldg(log_var + l), -3.0f);
    }
}

extern "C" void kernel_launch(void* const* d_in, const int* in_sizes, int n_in,
                              void* d_out, int out_size) {
    const float* hidden  = (const float*)d_in[0];
    const float* x       = (const float*)d_in[1];
    const float* mask    = (const float*)d_in[2];
    const float* Wir     = (const float*)d_in[3];
    const float* bir     = (const float*)d_in[4];
    const float* Wiz     = (const float*)d_in[5];
    const float* biz     = (const float*)d_in[6];
    const float* Win     = (const float*)d_in[7];
    const float* bin_    = (const float*)d_in[8];
    const float* Whr     = (const float*)d_in[9];
    const float* Whz     = (const float*)d_in[10];
    const float* Whn     = (const float*)d_in[11];
    const float* bhn     = (const float*)d_in[12];
    const float* W1      = (const float*)d_in[13];
    const float* b1      = (const float*)d_in[14];
    const float* W2      = (const float*)d_in[15];
    const float* b2      = (const float*)d_in[16];
    const float* Wmu     = (const float*)d_in[17];
    const float* bmu     = (const float*)d_in[18];
    const float* log_var = (const float*)d_in[19];
    float* out = (float*)d_out;

    cudaFuncSetAttribute(prnn_xi, cudaFuncAttributeMaxDynamicSharedMemorySize,
                         SMEM_XI);
    cudaFuncSetAttribute(prnn_main, cudaFuncAttributeMaxDynamicSharedMemorySize,
                         SMEM_MAIN);
    wprep<<<2944, 256>>>(Whr, Whn, Whz, W1, W2, Wir, Win, Wiz);
    prnn_xi<<<1024, 512, SMEM_XI>>>(x, mask, bir, bin_, biz);
    prnn_main<<<2048, 256, SMEM_MAIN>>>(hidden, bhn, b1, b2, Wmu, bmu,
                                        log_var, out);
}